// round 16
// baseline (speedup 1.0000x reference)
#include <cuda_runtime.h>
#include <cuda_fp16.h>
#include <cstdint>

#define N_NODES 100000
#define N_EDGES 1600000

// Ping-pong node-feature buffers. bufA holds f32 D=32 (layer1) then f16 D=64
// (layer2 intermediate); bufB holds f16 D=64 (post-relu layer1 output).
__device__ float g_bufA[(size_t)N_NODES * 64];
__device__ float g_bufB[(size_t)N_NODES * 64];

// CSR scratch (graph identical across all 4 SpMMs -> build once per launch).
// g_deg is zero on entry to every launch: static zero-init covers the first
// call, and scan_kernel re-zeroes it after consuming it on every call.
__device__ int    g_deg[N_NODES];
__device__ int    g_rowstart[N_NODES + 1];
__device__ int    g_cursor[N_NODES];
__device__ float2 g_epack[N_EDGES];   // {.x = __int_as_float(col), .y = 0.5f*val}

// ---------------------------------------------------------------------------
// CSR build kernel 1: degree histogram.
// ---------------------------------------------------------------------------
__global__ void hist_kernel(const int* __restrict__ erow) {
    int i = blockIdx.x * blockDim.x + threadIdx.x;
    if (i < N_EDGES) atomicAdd(&g_deg[erow[i]], 1);
}

// ---------------------------------------------------------------------------
// CSR build kernel 2: single-block exclusive scan of g_deg -> g_rowstart,
// init g_cursor, zero g_deg (leaves it clean for the next launch).
// 1024 threads, 98 coalesced tiles, shfl block-scan + register carry.
// ---------------------------------------------------------------------------
__global__ void scan_kernel() {
    __shared__ int warp_tot[32];
    int tid = threadIdx.x, lane = tid & 31, warp = tid >> 5;
    int carry = 0;

    for (int base = 0; base < N_NODES; base += 1024) {
        int idx = base + tid;
        int v = (idx < N_NODES) ? g_deg[idx] : 0;

        int x = v;  // warp inclusive scan
#pragma unroll
        for (int off = 1; off < 32; off <<= 1) {
            int t = __shfl_up_sync(0xFFFFFFFFu, x, off);
            if (lane >= off) x += t;
        }
        if (lane == 31) warp_tot[warp] = x;
        __syncthreads();
        if (warp == 0) {
            int s = warp_tot[lane];
#pragma unroll
            for (int off = 1; off < 32; off <<= 1) {
                int t = __shfl_up_sync(0xFFFFFFFFu, s, off);
                if (lane >= off) s += t;
            }
            warp_tot[lane] = s;   // inclusive totals over warps
        }
        __syncthreads();

        int wbase = warp ? warp_tot[warp - 1] : 0;
        int excl = carry + wbase + x - v;
        if (idx < N_NODES) {
            g_rowstart[idx] = excl;
            g_cursor[idx] = excl;
            g_deg[idx] = 0;
        }
        carry += warp_tot[31];
        __syncthreads();   // protect warp_tot before next tile overwrites
    }
    if (tid == 0) g_rowstart[N_NODES] = N_EDGES;
}

// ---------------------------------------------------------------------------
// CSR build kernel 3: scatter packed edges into row-grouped order.
// ---------------------------------------------------------------------------
__global__ void scatter_edges_kernel(const int* __restrict__ erow,
                                     const int* __restrict__ ecol,
                                     const float* __restrict__ eval) {
    int i = blockIdx.x * blockDim.x + threadIdx.x;
    if (i >= N_EDGES) return;
    int r = erow[i];
    int p = atomicAdd(&g_cursor[r], 1);
    float2 pk;
    pk.x = __int_as_float(ecol[i]);
    pk.y = 0.5f * eval[i];
    g_epack[p] = pk;
}

// ---------------------------------------------------------------------------
// f32 warp-level row reduce, D=32: C=8 f4-chunks, SUBS=4 edge lanes, unroll x2.
// Returns reduced chunk in lanes with sub==0.  (R12 best-known config.)
// ---------------------------------------------------------------------------
__device__ __forceinline__ float4 row_reduce32f(const float4* __restrict__ src,
                                                int row, int sub, int c) {
    constexpr int SUBS = 4;
    int start = g_rowstart[row];
    int end   = g_rowstart[row + 1];

    float4 a0 = make_float4(0.f, 0.f, 0.f, 0.f);
    float4 a1 = make_float4(0.f, 0.f, 0.f, 0.f);
    int e = start + sub;
    for (; e + SUBS < end; e += 2 * SUBS) {
        float2 ev0 = __ldg(&g_epack[e]);
        float2 ev1 = __ldg(&g_epack[e + SUBS]);
        float4 g0 = __ldg(&src[(size_t)__float_as_int(ev0.x) * 8 + c]);
        float4 g1 = __ldg(&src[(size_t)__float_as_int(ev1.x) * 8 + c]);
        float v0 = ev0.y, v1 = ev1.y;
        a0.x = fmaf(v0, g0.x, a0.x);  a0.y = fmaf(v0, g0.y, a0.y);
        a0.z = fmaf(v0, g0.z, a0.z);  a0.w = fmaf(v0, g0.w, a0.w);
        a1.x = fmaf(v1, g1.x, a1.x);  a1.y = fmaf(v1, g1.y, a1.y);
        a1.z = fmaf(v1, g1.z, a1.z);  a1.w = fmaf(v1, g1.w, a1.w);
    }
    if (e < end) {
        float2 ev = __ldg(&g_epack[e]);
        float4 g = __ldg(&src[(size_t)__float_as_int(ev.x) * 8 + c]);
        float v = ev.y;
        a0.x = fmaf(v, g.x, a0.x);  a0.y = fmaf(v, g.y, a0.y);
        a0.z = fmaf(v, g.z, a0.z);  a0.w = fmaf(v, g.w, a0.w);
    }
    a0.x += a1.x; a0.y += a1.y; a0.z += a1.z; a0.w += a1.w;

#pragma unroll
    for (int off = 8; off < 32; off <<= 1) {
        a0.x += __shfl_xor_sync(0xFFFFFFFFu, a0.x, off);
        a0.y += __shfl_xor_sync(0xFFFFFFFFu, a0.y, off);
        a0.z += __shfl_xor_sync(0xFFFFFFFFu, a0.z, off);
        a0.w += __shfl_xor_sync(0xFFFFFFFFu, a0.w, off);
    }
    return a0;
}

// ---------------------------------------------------------------------------
// f16 fma helper: g = 8 packed halfs; accumulate v*g into lo/hi float4.
// ---------------------------------------------------------------------------
__device__ __forceinline__ void fma8h(float4 g, float v, float4& lo, float4& hi) {
    const __half2* h = reinterpret_cast<const __half2*>(&g);
    float2 p;
    p = __half22float2(h[0]); lo.x = fmaf(v, p.x, lo.x); lo.y = fmaf(v, p.y, lo.y);
    p = __half22float2(h[1]); lo.z = fmaf(v, p.x, lo.z); lo.w = fmaf(v, p.y, lo.w);
    p = __half22float2(h[2]); hi.x = fmaf(v, p.x, hi.x); hi.y = fmaf(v, p.y, hi.y);
    p = __half22float2(h[3]); hi.z = fmaf(v, p.x, hi.z); hi.w = fmaf(v, p.y, hi.w);
}

// ---------------------------------------------------------------------------
// f16 warp-level row reduce, D=64: C=8 f4-chunks, SUBS=4, unroll x2.
// (R12 best-known config.)
// ---------------------------------------------------------------------------
__device__ __forceinline__ void row_reduce64h(const float4* __restrict__ src,
                                              int row, int sub, int c,
                                              float4& lo_out, float4& hi_out) {
    constexpr int SUBS = 4;
    int start = g_rowstart[row];
    int end   = g_rowstart[row + 1];

    float4 l0 = make_float4(0.f, 0.f, 0.f, 0.f), h0 = l0;
    float4 l1 = l0, h1 = l0;
    int e = start + sub;
    for (; e + SUBS < end; e += 2 * SUBS) {
        float2 ev0 = __ldg(&g_epack[e]);
        float2 ev1 = __ldg(&g_epack[e + SUBS]);
        float4 g0 = __ldg(&src[(size_t)__float_as_int(ev0.x) * 8 + c]);
        float4 g1 = __ldg(&src[(size_t)__float_as_int(ev1.x) * 8 + c]);
        fma8h(g0, ev0.y, l0, h0);
        fma8h(g1, ev1.y, l1, h1);
    }
    if (e < end) {
        float2 ev = __ldg(&g_epack[e]);
        float4 g = __ldg(&src[(size_t)__float_as_int(ev.x) * 8 + c]);
        fma8h(g, ev.y, l0, h0);
    }
    l0.x += l1.x; l0.y += l1.y; l0.z += l1.z; l0.w += l1.w;
    h0.x += h1.x; h0.y += h1.y; h0.z += h1.z; h0.w += h1.w;

#pragma unroll
    for (int off = 8; off < 32; off <<= 1) {
        l0.x += __shfl_xor_sync(0xFFFFFFFFu, l0.x, off);
        l0.y += __shfl_xor_sync(0xFFFFFFFFu, l0.y, off);
        l0.z += __shfl_xor_sync(0xFFFFFFFFu, l0.z, off);
        l0.w += __shfl_xor_sync(0xFFFFFFFFu, l0.w, off);
        h0.x += __shfl_xor_sync(0xFFFFFFFFu, h0.x, off);
        h0.y += __shfl_xor_sync(0xFFFFFFFFu, h0.y, off);
        h0.z += __shfl_xor_sync(0xFFFFFFFFu, h0.z, off);
        h0.w += __shfl_xor_sync(0xFFFFFFFFu, h0.w, off);
    }
    lo_out = l0; hi_out = h0;
}

// ---------------------------------------------------------------------------
// Pass 1: SpMM D=32 f32, x -> bufA. One warp per row.
// ---------------------------------------------------------------------------
__global__ void spmm_gather32_kernel(const float* __restrict__ x) {
    const float4* __restrict__ src = reinterpret_cast<const float4*>(x);
    float4* dst = reinterpret_cast<float4*>(g_bufA);

    int warp_id = (blockIdx.x * blockDim.x + threadIdx.x) >> 5;
    if (warp_id >= N_NODES) return;
    int lane = threadIdx.x & 31;
    int sub = lane >> 3, c = lane & 7;

    float4 acc = row_reduce32f(src, warp_id, sub, c);
    if (sub == 0) dst[(size_t)warp_id * 8 + c] = acc;
}

// ---------------------------------------------------------------------------
// Pass 2: fused SpMM(D=32 f32, bufA) + linear(32->64) + relu -> bufB (f16).
// 256 threads = 8 warps = 8 rows; warp-private srow + __syncwarp.
// ---------------------------------------------------------------------------
__global__ void spmm_linear32_kernel(const float* __restrict__ W,
                                     const float* __restrict__ b) {
    constexpr int WARPS = 8;
    __shared__ __align__(16) float sW[32][64];
    __shared__ __align__(16) float sbias[64];
    __shared__ __align__(16) float srow[WARPS][32];

    const float4* __restrict__ src = reinterpret_cast<const float4*>(g_bufA);
    __half2* dst = reinterpret_cast<__half2*>(g_bufB);

    int tid = threadIdx.x;
    for (int k = tid; k < 32 * 64; k += 256) sW[k >> 6][k & 63] = W[k];
    if (tid < 64) sbias[tid] = b[tid];
    __syncthreads();

    int warp = tid >> 5, lane = tid & 31;
    int row = blockIdx.x * WARPS + warp;   // 100000 = 12500 * 8, exact
    int sub = lane >> 3, c = lane & 7;

    float4 acc = row_reduce32f(src, row, sub, c);
    if (sub == 0) reinterpret_cast<float4*>(srow[warp])[c] = acc;
    __syncwarp();

    const float2* sW2 = reinterpret_cast<const float2*>(&sW[0][0]);
    float2 o = reinterpret_cast<const float2*>(sbias)[lane];
#pragma unroll
    for (int k = 0; k < 32; k++) {
        float r = srow[warp][k];
        float2 w = sW2[k * 32 + lane];
        o.x = fmaf(r, w.x, o.x);
        o.y = fmaf(r, w.y, o.y);
    }
    o.x = fmaxf(o.x, 0.f);
    o.y = fmaxf(o.y, 0.f);
    dst[(size_t)row * 32 + lane] = __floats2half2_rn(o.x, o.y);
}

// ---------------------------------------------------------------------------
// Pass 3: SpMM D=64 f16, bufB -> bufA (f16). One warp per row, SUBS=4.
// ---------------------------------------------------------------------------
__global__ void spmm_gather64h_kernel() {
    const float4* __restrict__ src = reinterpret_cast<const float4*>(g_bufB);
    float4* dst = reinterpret_cast<float4*>(g_bufA);

    int warp_id = (blockIdx.x * blockDim.x + threadIdx.x) >> 5;
    if (warp_id >= N_NODES) return;
    int lane = threadIdx.x & 31;
    int sub = lane >> 3, c = lane & 7;

    float4 lo, hi;
    row_reduce64h(src, warp_id, sub, c, lo, hi);
    if (sub == 0) {
        float4 pk;
        __half2* p = reinterpret_cast<__half2*>(&pk);
        p[0] = __floats2half2_rn(lo.x, lo.y);
        p[1] = __floats2half2_rn(lo.z, lo.w);
        p[2] = __floats2half2_rn(hi.x, hi.y);
        p[3] = __floats2half2_rn(hi.z, hi.w);
        dst[(size_t)warp_id * 8 + c] = pk;
    }
}

// ---------------------------------------------------------------------------
// Pass 4: fused SpMM(D=64 f16, bufA) + linear(64->64) + bias -> out (f32).
// ---------------------------------------------------------------------------
__global__ void spmm_linear64h_kernel(float* __restrict__ out,
                                      const float* __restrict__ W,
                                      const float* __restrict__ b) {
    constexpr int WARPS = 8;
    __shared__ __align__(16) float sW[64][64];
    __shared__ __align__(16) float sbias[64];
    __shared__ __align__(16) float srow[WARPS][64];

    const float4* __restrict__ src = reinterpret_cast<const float4*>(g_bufA);

    int tid = threadIdx.x;
    for (int k = tid; k < 64 * 64; k += 256) sW[k >> 6][k & 63] = W[k];
    if (tid < 64) sbias[tid] = b[tid];
    __syncthreads();

    int warp = tid >> 5, lane = tid & 31;
    int row = blockIdx.x * WARPS + warp;   // exact
    int sub = lane >> 3, c = lane & 7;

    float4 lo, hi;
    row_reduce64h(src, row, sub, c, lo, hi);
    if (sub == 0) {
        float4* s4 = reinterpret_cast<float4*>(srow[warp]);
        s4[2 * c]     = lo;   // cols 8c .. 8c+3
        s4[2 * c + 1] = hi;   // cols 8c+4 .. 8c+7
    }
    __syncwarp();

    const float2* sW2 = reinterpret_cast<const float2*>(&sW[0][0]);
    float2 o = reinterpret_cast<const float2*>(sbias)[lane];
#pragma unroll
    for (int k = 0; k < 64; k++) {
        float r = srow[warp][k];
        float2 w = sW2[k * 32 + lane];
        o.x = fmaf(r, w.x, o.x);
        o.y = fmaf(r, w.y, o.y);
    }
    reinterpret_cast<float2*>(out)[(size_t)row * 32 + lane] = o;
}

// ---------------------------------------------------------------------------
// Launch sequence (7 kernels):
//   hist -> scan (1 block; also inits cursors, zeroes deg) -> scatter
//   bufA(f32,32) <- spmm(x)
//   bufB(f16,64) <- relu(spmm(bufA) @ W1 + b1)     (fused)
//   bufA(f16,64) <- spmm(bufB)
//   out(f32)     <- spmm(bufA) @ W2 + b2           (fused)
// ---------------------------------------------------------------------------
extern "C" void kernel_launch(void* const* d_in, const int* in_sizes, int n_in,
                              void* d_out, int out_size) {
    const float* x    = (const float*)d_in[0];
    const float* evl  = (const float*)d_in[1];
    const int*   erow = (const int*)  d_in[2];
    const int*   ecol = (const int*)  d_in[3];
    const float* W1   = (const float*)d_in[4];
    const float* b1   = (const float*)d_in[5];
    const float* W2   = (const float*)d_in[6];
    const float* b2   = (const float*)d_in[7];
    float* out = (float*)d_out;

    const int TPB = 256;
    int edge_blocks = (N_EDGES + TPB - 1) / TPB;
    int warp_blocks = (N_NODES * 32 + TPB - 1) / TPB;   // 12500
    int fused_blocks = N_NODES / 8;                      // 12500

    // --- CSR build (3 kernels) ---
    hist_kernel<<<edge_blocks, TPB>>>(erow);
    scan_kernel<<<1, 1024>>>();
    scatter_edges_kernel<<<edge_blocks, TPB>>>(erow, ecol, evl);

    // --- layer 1 ---
    spmm_gather32_kernel<<<warp_blocks, TPB>>>(x);
    spmm_linear32_kernel<<<fused_blocks, TPB>>>(W1, b1);

    // --- layer 2 (f16 features) ---
    spmm_gather64h_kernel<<<warp_blocks, TPB>>>();
    spmm_linear64h_kernel<<<fused_blocks, TPB>>>(out, W2, b2);
}

// round 17
// speedup vs baseline: 1.3942x; 1.3942x over previous
#include <cuda_runtime.h>
#include <cuda_fp16.h>
#include <cstdint>

#define N_NODES 100000
#define N_EDGES 1600000
#define SCAN_BS 1024
#define SCAN_NB ((N_NODES + SCAN_BS - 1) / SCAN_BS)   // 98

// Ping-pong node-feature buffers. bufA holds f32 D=32 (layer1) then f16 D=64
// (layer2 intermediate); bufB holds f16 D=64 (post-relu layer1 output).
__device__ float g_bufA[(size_t)N_NODES * 64];
__device__ float g_bufB[(size_t)N_NODES * 64];

// CSR scratch (graph identical across all 4 SpMMs -> build once per launch).
// g_deg is zero on entry to every launch: static zero-init covers the first
// call; scan_local_kernel re-zeroes it after consuming it on every call.
__device__ int    g_deg[N_NODES];
__device__ int    g_rowstart[N_NODES + 1];
__device__ int    g_cursor[N_NODES];
__device__ int    g_bsums[128];
__device__ float2 g_epack[N_EDGES];   // {.x = __int_as_float(col), .y = 0.5f*val}

// ---------------------------------------------------------------------------
// CSR build
// ---------------------------------------------------------------------------
__global__ void hist_kernel(const int* __restrict__ erow) {
    int i = blockIdx.x * blockDim.x + threadIdx.x;
    if (i < N_EDGES) atomicAdd(&g_deg[erow[i]], 1);
}

// Per-block inclusive scan (Hillis-Steele over 1024), write exclusive result.
// Also zeroes g_deg after consuming it (replaces the zero_deg kernel).
__global__ void scan_local_kernel() {
    __shared__ int s[SCAN_BS];
    int tid = threadIdx.x;
    int idx = blockIdx.x * SCAN_BS + tid;
    int v = (idx < N_NODES) ? g_deg[idx] : 0;
    s[tid] = v;
    __syncthreads();
#pragma unroll
    for (int off = 1; off < SCAN_BS; off <<= 1) {
        int t = (tid >= off) ? s[tid - off] : 0;
        __syncthreads();
        s[tid] += t;
        __syncthreads();
    }
    if (idx < N_NODES) {
        g_rowstart[idx] = s[tid] - v;   // exclusive
        g_deg[idx] = 0;                  // clean for next launch
    }
    if (tid == SCAN_BS - 1) g_bsums[blockIdx.x] = s[tid];
}

// Every block redundantly scans the 98 block sums, applies prefix, inits cursors.
__global__ void scan_add_kernel() {
    __shared__ int sb[128];
    int tid = threadIdx.x;   // 256 threads
    if (tid < 128) sb[tid] = (tid < SCAN_NB) ? g_bsums[tid] : 0;
    __syncthreads();
#pragma unroll
    for (int off = 1; off < 128; off <<= 1) {
        int t = (tid < 128 && tid >= off) ? sb[tid - off] : 0;
        __syncthreads();
        if (tid < 128) sb[tid] += t;
        __syncthreads();
    }
    int idx = blockIdx.x * blockDim.x + tid;
    if (idx < N_NODES) {
        int blk = idx >> 10;
        int add = (blk == 0) ? 0 : sb[blk - 1];
        int r = g_rowstart[idx] + add;
        g_rowstart[idx] = r;
        g_cursor[idx] = r;
    }
    if (idx == 0) g_rowstart[N_NODES] = N_EDGES;
}

__global__ void scatter_edges_kernel(const int* __restrict__ erow,
                                     const int* __restrict__ ecol,
                                     const float* __restrict__ eval) {
    int i = blockIdx.x * blockDim.x + threadIdx.x;
    if (i >= N_EDGES) return;
    int r = erow[i];
    int p = atomicAdd(&g_cursor[r], 1);
    float2 pk;
    pk.x = __int_as_float(ecol[i]);
    pk.y = 0.5f * eval[i];
    g_epack[p] = pk;
}

// ---------------------------------------------------------------------------
// f32 warp-level row reduce, D=32: C=8 f4-chunks, SUBS=4 edge lanes, unroll x2.
// Returns reduced chunk in lanes with sub==0.  (R12 best-known config.)
// ---------------------------------------------------------------------------
__device__ __forceinline__ float4 row_reduce32f(const float4* __restrict__ src,
                                                int row, int sub, int c) {
    constexpr int SUBS = 4;
    int start = g_rowstart[row];
    int end   = g_rowstart[row + 1];

    float4 a0 = make_float4(0.f, 0.f, 0.f, 0.f);
    float4 a1 = make_float4(0.f, 0.f, 0.f, 0.f);
    int e = start + sub;
    for (; e + SUBS < end; e += 2 * SUBS) {
        float2 ev0 = __ldg(&g_epack[e]);
        float2 ev1 = __ldg(&g_epack[e + SUBS]);
        float4 g0 = __ldg(&src[(size_t)__float_as_int(ev0.x) * 8 + c]);
        float4 g1 = __ldg(&src[(size_t)__float_as_int(ev1.x) * 8 + c]);
        float v0 = ev0.y, v1 = ev1.y;
        a0.x = fmaf(v0, g0.x, a0.x);  a0.y = fmaf(v0, g0.y, a0.y);
        a0.z = fmaf(v0, g0.z, a0.z);  a0.w = fmaf(v0, g0.w, a0.w);
        a1.x = fmaf(v1, g1.x, a1.x);  a1.y = fmaf(v1, g1.y, a1.y);
        a1.z = fmaf(v1, g1.z, a1.z);  a1.w = fmaf(v1, g1.w, a1.w);
    }
    if (e < end) {
        float2 ev = __ldg(&g_epack[e]);
        float4 g = __ldg(&src[(size_t)__float_as_int(ev.x) * 8 + c]);
        float v = ev.y;
        a0.x = fmaf(v, g.x, a0.x);  a0.y = fmaf(v, g.y, a0.y);
        a0.z = fmaf(v, g.z, a0.z);  a0.w = fmaf(v, g.w, a0.w);
    }
    a0.x += a1.x; a0.y += a1.y; a0.z += a1.z; a0.w += a1.w;

#pragma unroll
    for (int off = 8; off < 32; off <<= 1) {
        a0.x += __shfl_xor_sync(0xFFFFFFFFu, a0.x, off);
        a0.y += __shfl_xor_sync(0xFFFFFFFFu, a0.y, off);
        a0.z += __shfl_xor_sync(0xFFFFFFFFu, a0.z, off);
        a0.w += __shfl_xor_sync(0xFFFFFFFFu, a0.w, off);
    }
    return a0;
}

// ---------------------------------------------------------------------------
// f16 fma helper: g = 8 packed halfs; accumulate v*g into lo/hi float4.
// ---------------------------------------------------------------------------
__device__ __forceinline__ void fma8h(float4 g, float v, float4& lo, float4& hi) {
    const __half2* h = reinterpret_cast<const __half2*>(&g);
    float2 p;
    p = __half22float2(h[0]); lo.x = fmaf(v, p.x, lo.x); lo.y = fmaf(v, p.y, lo.y);
    p = __half22float2(h[1]); lo.z = fmaf(v, p.x, lo.z); lo.w = fmaf(v, p.y, lo.w);
    p = __half22float2(h[2]); hi.x = fmaf(v, p.x, hi.x); hi.y = fmaf(v, p.y, hi.y);
    p = __half22float2(h[3]); hi.z = fmaf(v, p.x, hi.z); hi.w = fmaf(v, p.y, hi.w);
}

// ---------------------------------------------------------------------------
// f16 warp-level row reduce, D=64: C=8 f4-chunks, SUBS=4, unroll x2.
// ---------------------------------------------------------------------------
__device__ __forceinline__ void row_reduce64h(const float4* __restrict__ src,
                                              int row, int sub, int c,
                                              float4& lo_out, float4& hi_out) {
    constexpr int SUBS = 4;
    int start = g_rowstart[row];
    int end   = g_rowstart[row + 1];

    float4 l0 = make_float4(0.f, 0.f, 0.f, 0.f), h0 = l0;
    float4 l1 = l0, h1 = l0;
    int e = start + sub;
    for (; e + SUBS < end; e += 2 * SUBS) {
        float2 ev0 = __ldg(&g_epack[e]);
        float2 ev1 = __ldg(&g_epack[e + SUBS]);
        float4 g0 = __ldg(&src[(size_t)__float_as_int(ev0.x) * 8 + c]);
        float4 g1 = __ldg(&src[(size_t)__float_as_int(ev1.x) * 8 + c]);
        fma8h(g0, ev0.y, l0, h0);
        fma8h(g1, ev1.y, l1, h1);
    }
    if (e < end) {
        float2 ev = __ldg(&g_epack[e]);
        float4 g = __ldg(&src[(size_t)__float_as_int(ev.x) * 8 + c]);
        fma8h(g, ev.y, l0, h0);
    }
    l0.x += l1.x; l0.y += l1.y; l0.z += l1.z; l0.w += l1.w;
    h0.x += h1.x; h0.y += h1.y; h0.z += h1.z; h0.w += h1.w;

#pragma unroll
    for (int off = 8; off < 32; off <<= 1) {
        l0.x += __shfl_xor_sync(0xFFFFFFFFu, l0.x, off);
        l0.y += __shfl_xor_sync(0xFFFFFFFFu, l0.y, off);
        l0.z += __shfl_xor_sync(0xFFFFFFFFu, l0.z, off);
        l0.w += __shfl_xor_sync(0xFFFFFFFFu, l0.w, off);
        h0.x += __shfl_xor_sync(0xFFFFFFFFu, h0.x, off);
        h0.y += __shfl_xor_sync(0xFFFFFFFFu, h0.y, off);
        h0.z += __shfl_xor_sync(0xFFFFFFFFu, h0.z, off);
        h0.w += __shfl_xor_sync(0xFFFFFFFFu, h0.w, off);
    }
    lo_out = l0; hi_out = h0;
}

// ---------------------------------------------------------------------------
// Pass 1: SpMM D=32 f32, x -> bufA. One warp per row.
// ---------------------------------------------------------------------------
__global__ void spmm_gather32_kernel(const float* __restrict__ x) {
    const float4* __restrict__ src = reinterpret_cast<const float4*>(x);
    float4* dst = reinterpret_cast<float4*>(g_bufA);

    int warp_id = (blockIdx.x * blockDim.x + threadIdx.x) >> 5;
    if (warp_id >= N_NODES) return;
    int lane = threadIdx.x & 31;
    int sub = lane >> 3, c = lane & 7;

    float4 acc = row_reduce32f(src, warp_id, sub, c);
    if (sub == 0) dst[(size_t)warp_id * 8 + c] = acc;
}

// ---------------------------------------------------------------------------
// Pass 2: fused SpMM(D=32 f32, bufA) + linear(32->64) + relu -> bufB (f16).
// 256 threads = 8 warps; each warp processes 4 rows sequentially, so W is
// staged once per 32 rows (W L2 traffic /4 vs 8-row blocks). No block
// barriers inside the row loop -> no cross-row imbalance coupling.
// ---------------------------------------------------------------------------
__global__ void spmm_linear32_kernel(const float* __restrict__ W,
                                     const float* __restrict__ b) {
    constexpr int WARPS = 8;
    constexpr int RPW = 4;   // rows per warp
    __shared__ __align__(16) float sW[32][64];
    __shared__ __align__(16) float sbias[64];
    __shared__ __align__(16) float srow[WARPS][32];

    const float4* __restrict__ src = reinterpret_cast<const float4*>(g_bufA);
    __half2* dst = reinterpret_cast<__half2*>(g_bufB);

    int tid = threadIdx.x;
    for (int k = tid; k < 32 * 64; k += 256) sW[k >> 6][k & 63] = W[k];
    if (tid < 64) sbias[tid] = b[tid];
    __syncthreads();

    int warp = tid >> 5, lane = tid & 31;
    int sub = lane >> 3, c = lane & 7;
    const float2* sW2 = reinterpret_cast<const float2*>(&sW[0][0]);
    float2 bias2 = reinterpret_cast<const float2*>(sbias)[lane];

#pragma unroll
    for (int rr = 0; rr < RPW; rr++) {
        int row = blockIdx.x * (WARPS * RPW) + rr * WARPS + warp;  // 100000=3125*32

        float4 acc = row_reduce32f(src, row, sub, c);
        if (sub == 0) reinterpret_cast<float4*>(srow[warp])[c] = acc;
        __syncwarp();

        float2 o = bias2;
#pragma unroll
        for (int k = 0; k < 32; k++) {
            float r = srow[warp][k];
            float2 w = sW2[k * 32 + lane];
            o.x = fmaf(r, w.x, o.x);
            o.y = fmaf(r, w.y, o.y);
        }
        o.x = fmaxf(o.x, 0.f);
        o.y = fmaxf(o.y, 0.f);
        dst[(size_t)row * 32 + lane] = __floats2half2_rn(o.x, o.y);
        __syncwarp();   // done reading srow before next row overwrites
    }
}

// ---------------------------------------------------------------------------
// Pass 3: SpMM D=64 f16, bufB -> bufA (f16). One warp per row, SUBS=4.
// ---------------------------------------------------------------------------
__global__ void spmm_gather64h_kernel() {
    const float4* __restrict__ src = reinterpret_cast<const float4*>(g_bufB);
    float4* dst = reinterpret_cast<float4*>(g_bufA);

    int warp_id = (blockIdx.x * blockDim.x + threadIdx.x) >> 5;
    if (warp_id >= N_NODES) return;
    int lane = threadIdx.x & 31;
    int sub = lane >> 3, c = lane & 7;

    float4 lo, hi;
    row_reduce64h(src, warp_id, sub, c, lo, hi);
    if (sub == 0) {
        float4 pk;
        __half2* p = reinterpret_cast<__half2*>(&pk);
        p[0] = __floats2half2_rn(lo.x, lo.y);
        p[1] = __floats2half2_rn(lo.z, lo.w);
        p[2] = __floats2half2_rn(hi.x, hi.y);
        p[3] = __floats2half2_rn(hi.z, hi.w);
        dst[(size_t)warp_id * 8 + c] = pk;
    }
}

// ---------------------------------------------------------------------------
// Pass 4: fused SpMM(D=64 f16, bufA) + linear(64->64) + bias -> out (f32).
// 4 rows per warp sequentially; W (16KB) staged once per 32 rows.
// ---------------------------------------------------------------------------
__global__ void spmm_linear64h_kernel(float* __restrict__ out,
                                      const float* __restrict__ W,
                                      const float* __restrict__ b) {
    constexpr int WARPS = 8;
    constexpr int RPW = 4;
    __shared__ __align__(16) float sW[64][64];
    __shared__ __align__(16) float sbias[64];
    __shared__ __align__(16) float srow[WARPS][64];

    const float4* __restrict__ src = reinterpret_cast<const float4*>(g_bufA);

    int tid = threadIdx.x;
    for (int k = tid; k < 64 * 64; k += 256) sW[k >> 6][k & 63] = W[k];
    if (tid < 64) sbias[tid] = b[tid];
    __syncthreads();

    int warp = tid >> 5, lane = tid & 31;
    int sub = lane >> 3, c = lane & 7;
    const float2* sW2 = reinterpret_cast<const float2*>(&sW[0][0]);
    float2 bias2 = reinterpret_cast<const float2*>(sbias)[lane];

#pragma unroll
    for (int rr = 0; rr < RPW; rr++) {
        int row = blockIdx.x * (WARPS * RPW) + rr * WARPS + warp;

        float4 lo, hi;
        row_reduce64h(src, row, sub, c, lo, hi);
        if (sub == 0) {
            float4* s4 = reinterpret_cast<float4*>(srow[warp]);
            s4[2 * c]     = lo;   // cols 8c .. 8c+3
            s4[2 * c + 1] = hi;   // cols 8c+4 .. 8c+7
        }
        __syncwarp();

        float2 o = bias2;
#pragma unroll
        for (int k = 0; k < 64; k++) {
            float r = srow[warp][k];
            float2 w = sW2[k * 32 + lane];
            o.x = fmaf(r, w.x, o.x);
            o.y = fmaf(r, w.y, o.y);
        }
        reinterpret_cast<float2*>(out)[(size_t)row * 32 + lane] = o;
        __syncwarp();
    }
}

// ---------------------------------------------------------------------------
// Launch sequence (8 kernels):
//   hist -> scan_local (also zeroes deg) -> scan_add -> scatter
//   bufA(f32,32) <- spmm(x)
//   bufB(f16,64) <- relu(spmm(bufA) @ W1 + b1)     (fused, 32 rows/block)
//   bufA(f16,64) <- spmm(bufB)
//   out(f32)     <- spmm(bufA) @ W2 + b2           (fused, 32 rows/block)
// ---------------------------------------------------------------------------
extern "C" void kernel_launch(void* const* d_in, const int* in_sizes, int n_in,
                              void* d_out, int out_size) {
    const float* x    = (const float*)d_in[0];
    const float* evl  = (const float*)d_in[1];
    const int*   erow = (const int*)  d_in[2];
    const int*   ecol = (const int*)  d_in[3];
    const float* W1   = (const float*)d_in[4];
    const float* b1   = (const float*)d_in[5];
    const float* W2   = (const float*)d_in[6];
    const float* b2   = (const float*)d_in[7];
    float* out = (float*)d_out;

    const int TPB = 256;
    int node_blocks = (N_NODES + TPB - 1) / TPB;
    int edge_blocks = (N_EDGES + TPB - 1) / TPB;
    int warp_blocks = (N_NODES * 32 + TPB - 1) / TPB;   // 12500
    int fused_blocks = N_NODES / 32;                     // 3125

    // --- CSR build ---
    hist_kernel<<<edge_blocks, TPB>>>(erow);
    scan_local_kernel<<<SCAN_NB, SCAN_BS>>>();
    scan_add_kernel<<<node_blocks, TPB>>>();
    scatter_edges_kernel<<<edge_blocks, TPB>>>(erow, ecol, evl);

    // --- layer 1 ---
    spmm_gather32_kernel<<<warp_blocks, TPB>>>(x);
    spmm_linear32_kernel<<<fused_blocks, TPB>>>(W1, b1);

    // --- layer 2 (f16 features) ---
    spmm_gather64h_kernel<<<warp_blocks, TPB>>>();
    spmm_linear64h_kernel<<<fused_blocks, TPB>>>(out, W2, b2);
}